// round 15
// baseline (speedup 1.0000x reference)
#include <cuda_runtime.h>
#include <cuda_fp16.h>
#include <cstdint>

// Int4Linear via fp16 mma.sync.m16n8k16 (fp32 accum).
// R14 skeleton (CTA 128x128, 4 warps @ 64x64, BK=32, fused prepass) with
// NSTAGE=3 + __launch_bounds__(128,3) -> 3 CTAs/SM (12 warps) for latency
// hiding; ncu showed L1 at 48.5% (headroom) and occupancy as the limiter.
// Shapes: M = 4096, K = 4096, N = 11008, group = 64.

#define M_DIM 4096
#define N_DIM 11008
#define K_DIM 4096
#define GRP   64

#define BM 128
#define BN 128
#define BK 32
#define NITER (K_DIM / BK)        // 128
#define NSTAGE 3
#define SROWH 40                  // halves per smem row: 32 + 8 pad (conflict-free)
#define TILEH (128 * SROWH)       // halves per (A or B) stage tile
#define SMEM_SZ (NSTAGE * 2 * TILEH * 2)   // 61440 bytes -> 3 CTAs/SM (184 KB)

__device__ __half g_wh[(size_t)N_DIM * K_DIM];   // 90 MB dequantized W
__device__ __half g_xh[(size_t)M_DIM * K_DIM];   // 32 MB x in fp16

#define DEQ_BLOCKS ((int)(((size_t)N_DIM * K_DIM / 8) / 256))   // 22016
#define CVT_BLOCKS ((int)(((size_t)M_DIM * K_DIM / 8) / 256))   // 8192

__device__ __forceinline__ uint32_t smem_u32(const void* p) {
    uint32_t a;
    asm("{ .reg .u64 t; cvta.to.shared.u64 t, %1; cvt.u32.u64 %0, t; }"
        : "=r"(a) : "l"(p));
    return a;
}
#define CP_ASYNC16(dst, src) \
    asm volatile("cp.async.cg.shared.global [%0], [%1], 16;" \
                 :: "r"(dst), "l"(src) : "memory")
#define CP_COMMIT() asm volatile("cp.async.commit_group;" ::: "memory")

__device__ __forceinline__ void ldsm_x4(uint32_t* r, uint32_t addr) {
    asm volatile("ldmatrix.sync.aligned.m8n8.x4.shared.b16 {%0,%1,%2,%3}, [%4];"
                 : "=r"(r[0]), "=r"(r[1]), "=r"(r[2]), "=r"(r[3]) : "r"(addr));
}
__device__ __forceinline__ void mma_fp16(float* d, const uint32_t* a,
                                         uint32_t b0, uint32_t b1) {
    asm volatile(
        "mma.sync.aligned.m16n8k16.row.col.f32.f16.f16.f32 "
        "{%0,%1,%2,%3}, {%4,%5,%6,%7}, {%8,%9}, {%0,%1,%2,%3};"
        : "+f"(d[0]), "+f"(d[1]), "+f"(d[2]), "+f"(d[3])
        : "r"(a[0]), "r"(a[1]), "r"(a[2]), "r"(a[3]), "r"(b0), "r"(b1));
}

// -------- fused prepass: blocks [0, DEQ) dequant W; [DEQ, DEQ+CVT) convert x --------
__global__ __launch_bounds__(256)
void prepass_kernel(const float* __restrict__ x,
                    const int* __restrict__ packed,
                    const float* __restrict__ scales,
                    const int* __restrict__ zeros)
{
    if (blockIdx.x < DEQ_BLOCKS) {
        size_t idx = (size_t)blockIdx.x * 256 + threadIdx.x;   // over N*K/8
        int n  = (int)(idx >> 9);
        int j4 = (int)(idx & 511);                             // 4 int32 -> 8 k
        int4 p = *reinterpret_cast<const int4*>(
            &packed[(size_t)n * (K_DIM / 2) + j4 * 4]);
        int g  = j4 >> 3;
        float s  = scales[(size_t)n * (K_DIM / GRP) + g];
        float zs = -(float)zeros[(size_t)n * (K_DIM / GRP) + g] * s;
        int pv[4] = {p.x, p.y, p.z, p.w};
        __half2 h[4];
        #pragma unroll
        for (int c = 0; c < 4; c++)
            h[c] = __floats2half2_rn((float)( pv[c]       & 15) * s + zs,
                                     (float)((pv[c] >> 4) & 15) * s + zs);
        *reinterpret_cast<uint4*>(&g_wh[(size_t)n * K_DIM + j4 * 8]) =
            *reinterpret_cast<uint4*>(h);
    } else {
        size_t idx = (size_t)(blockIdx.x - DEQ_BLOCKS) * 256 + threadIdx.x;
        const float4 v0 = *reinterpret_cast<const float4*>(x + idx * 8);
        const float4 v1 = *reinterpret_cast<const float4*>(x + idx * 8 + 4);
        __half2 h[4];
        h[0] = __floats2half2_rn(v0.x, v0.y);
        h[1] = __floats2half2_rn(v0.z, v0.w);
        h[2] = __floats2half2_rn(v1.x, v1.y);
        h[3] = __floats2half2_rn(v1.z, v1.w);
        *reinterpret_cast<uint4*>(&g_xh[idx * 8]) = *reinterpret_cast<uint4*>(h);
    }
}

// -------- GEMM: 128 threads, 64x64 warp tiles, 3 CTAs/SM --------
__global__ __launch_bounds__(128, 3)
void gemm_fp16_kernel(const float* __restrict__ bias,
                      float* __restrict__ out)
{
    extern __shared__ __align__(16) __half smem[];
    __half* As = smem;                       // [NSTAGE][128][SROWH]
    __half* Bs = smem + NSTAGE * TILEH;

    const int tid    = threadIdx.x;
    const int lane   = tid & 31;
    const int wid    = tid >> 5;
    const int warp_m = wid & 1;              // 2 warps in m -> 64 rows each
    const int warp_n = wid >> 1;             // 2 warps in n -> 64 cols each
    const int m0 = blockIdx.x * BM;
    const int n0 = blockIdx.y * BN;

    const uint32_t as_u = smem_u32(As);
    const uint32_t bs_u = smem_u32(Bs);

    // cp.async: each tile = 512 16B chunks; 128 threads -> 4 chunks/thread/tile
    const int ld_row = tid >> 2;             // 0..31, +32 per i
    const int ld_c16 = tid & 3;              // 16B col within 64B row
    const __half* a_src = g_xh + (size_t)(m0 + ld_row) * K_DIM + ld_c16 * 8;
    const __half* b_src = g_wh + (size_t)(n0 + ld_row) * K_DIM + ld_c16 * 8;
    const uint32_t a_dst0 = as_u + (uint32_t)(ld_row * SROWH) * 2 + ld_c16 * 16;
    const uint32_t b_dst0 = bs_u + (uint32_t)(ld_row * SROWH) * 2 + ld_c16 * 16;

    float acc[4][8][4];
    #pragma unroll
    for (int i = 0; i < 4; i++)
        #pragma unroll
        for (int j = 0; j < 8; j++)
            #pragma unroll
            for (int r = 0; r < 4; r++) acc[i][j][r] = 0.0f;

    // prologue: stages 0..NSTAGE-2
    #pragma unroll
    for (int s = 0; s < NSTAGE - 1; s++) {
        const int k0 = s * BK;
        #pragma unroll
        for (int i = 0; i < 4; i++) {
            CP_ASYNC16(a_dst0 + (uint32_t)(s * TILEH + i * 32 * SROWH) * 2,
                       a_src + (size_t)i * 32 * K_DIM + k0);
            CP_ASYNC16(b_dst0 + (uint32_t)(s * TILEH + i * 32 * SROWH) * 2,
                       b_src + (size_t)i * 32 * K_DIM + k0);
        }
        CP_COMMIT();
    }

    // ldmatrix bases
    const uint32_t a_frag0 = as_u +
        (uint32_t)((warp_m * 64 + (lane & 15)) * SROWH + (lane >> 4) * 8) * 2;
    const uint32_t b_frag0 = bs_u +
        (uint32_t)((warp_n * 64 + ((lane >> 4) * 8) + (lane & 7)) * SROWH +
                   (((lane >> 3) & 1) * 8)) * 2;

    for (int it = 0; it < NITER; ++it) {
        asm volatile("cp.async.wait_group %0;" :: "n"(NSTAGE - 2) : "memory");
        __syncthreads();

        // prefetch stage it+2 into buffer (it-1)%3 (consumed at it-1; all
        // warps passed this barrier) -> overlaps compute below
        const int pf = it + NSTAGE - 1;
        if (pf < NITER) {
            const int k0 = pf * BK;
            const uint32_t poff = (uint32_t)((pf % NSTAGE) * TILEH) * 2;
            #pragma unroll
            for (int i = 0; i < 4; i++) {
                CP_ASYNC16(a_dst0 + poff + (uint32_t)(i * 32 * SROWH) * 2,
                           a_src + (size_t)i * 32 * K_DIM + k0);
                CP_ASYNC16(b_dst0 + poff + (uint32_t)(i * 32 * SROWH) * 2,
                           b_src + (size_t)i * 32 * K_DIM + k0);
            }
        }
        CP_COMMIT();   // one group per iter keeps counts aligned

        const uint32_t soff = (uint32_t)((it % NSTAGE) * TILEH) * 2;

        #pragma unroll
        for (int ks = 0; ks < BK / 16; ks++) {
            uint32_t a[4][4], b[4][4];
            #pragma unroll
            for (int i = 0; i < 4; i++)
                ldsm_x4(a[i], a_frag0 + soff + (uint32_t)(i * 16 * SROWH + ks * 16) * 2);
            #pragma unroll
            for (int j2 = 0; j2 < 4; j2++)
                ldsm_x4(b[j2], b_frag0 + soff + (uint32_t)(j2 * 16 * SROWH + ks * 16) * 2);
            #pragma unroll
            for (int i = 0; i < 4; i++)
                #pragma unroll
                for (int j = 0; j < 8; j++)
                    mma_fp16(acc[i][j], a[i], b[j >> 1][(j & 1) * 2],
                             b[j >> 1][(j & 1) * 2 + 1]);
        }
    }

    // -------- epilogue: bias + store --------
    #pragma unroll
    for (int i = 0; i < 4; i++) {
        const int mrow = m0 + warp_m * 64 + i * 16 + (lane >> 2);
        #pragma unroll
        for (int j = 0; j < 8; j++) {
            const int n = n0 + warp_n * 64 + j * 8 + 2 * (lane & 3);
            const float b0 = bias[n], b1 = bias[n + 1];
            float2 v0 = make_float2(acc[i][j][0] + b0, acc[i][j][1] + b1);
            float2 v1 = make_float2(acc[i][j][2] + b0, acc[i][j][3] + b1);
            *reinterpret_cast<float2*>(out + (size_t)mrow * N_DIM + n) = v0;
            *reinterpret_cast<float2*>(out + (size_t)(mrow + 8) * N_DIM + n) = v1;
        }
    }
}

// -------- launch --------
extern "C" void kernel_launch(void* const* d_in, const int* in_sizes, int n_in,
                              void* d_out, int out_size)
{
    const float* x      = (const float*)d_in[0];
    const int*   packed = (const int*)  d_in[1];
    const float* scales = (const float*)d_in[2];
    const int*   zeros  = (const int*)  d_in[3];
    const float* bias   = (const float*)d_in[4];
    float*       out    = (float*)d_out;

    static int smem_set = 0;
    if (!smem_set) {
        cudaFuncSetAttribute(gemm_fp16_kernel,
                             cudaFuncAttributeMaxDynamicSharedMemorySize, SMEM_SZ);
        smem_set = 1;
    }

    prepass_kernel<<<DEQ_BLOCKS + CVT_BLOCKS, 256>>>(x, packed, scales, zeros);

    dim3 grid(M_DIM / BM, N_DIM / BN);   // 32 x 86; m fastest -> A stays L2-resident
    gemm_fp16_kernel<<<grid, 128, SMEM_SZ>>>(bias, out);
}

// round 16
// speedup vs baseline: 1.2213x; 1.2213x over previous
#include <cuda_runtime.h>
#include <cuda_fp16.h>
#include <cstdint>

// Int4Linear via fp16 mma.sync.m16n8k16 (fp32 accum).
// R14 skeleton (CTA 128x128, 4 warps @ 64x64, BK=32, NSTAGE=4, 2 CTAs/SM,
// fused prepass) + cross-iteration fragment pipelining:
//   wait_group 1 guarantees stage it+1 resident during iter it, so iter it's
//   tail loads iter it+1's ks=0 fragments (reusing the same registers after
//   the ks=0 MMAs) and every iteration BEGINS with MMAs instead of LDSMs.
// Shapes: M = 4096, K = 4096, N = 11008, group = 64.

#define M_DIM 4096
#define N_DIM 11008
#define K_DIM 4096
#define GRP   64

#define BM 128
#define BN 128
#define BK 32
#define NITER (K_DIM / BK)        // 128
#define NSTAGE 4
#define SROWH 40                  // halves per smem row: 32 + 8 pad (conflict-free)
#define TILEH (128 * SROWH)       // halves per (A or B) stage tile
#define SMEM_SZ (NSTAGE * 2 * TILEH * 2)   // 81920 bytes -> 2 CTAs/SM

__device__ __half g_wh[(size_t)N_DIM * K_DIM];   // 90 MB dequantized W
__device__ __half g_xh[(size_t)M_DIM * K_DIM];   // 32 MB x in fp16

#define DEQ_BLOCKS ((int)(((size_t)N_DIM * K_DIM / 8) / 256))   // 22016
#define CVT_BLOCKS ((int)(((size_t)M_DIM * K_DIM / 8) / 256))   // 8192

__device__ __forceinline__ uint32_t smem_u32(const void* p) {
    uint32_t a;
    asm("{ .reg .u64 t; cvta.to.shared.u64 t, %1; cvt.u32.u64 %0, t; }"
        : "=r"(a) : "l"(p));
    return a;
}
#define CP_ASYNC16(dst, src) \
    asm volatile("cp.async.cg.shared.global [%0], [%1], 16;" \
                 :: "r"(dst), "l"(src) : "memory")
#define CP_COMMIT() asm volatile("cp.async.commit_group;" ::: "memory")

__device__ __forceinline__ void ldsm_x4(uint32_t* r, uint32_t addr) {
    asm volatile("ldmatrix.sync.aligned.m8n8.x4.shared.b16 {%0,%1,%2,%3}, [%4];"
                 : "=r"(r[0]), "=r"(r[1]), "=r"(r[2]), "=r"(r[3]) : "r"(addr));
}
__device__ __forceinline__ void mma_fp16(float* d, const uint32_t* a,
                                         uint32_t b0, uint32_t b1) {
    asm volatile(
        "mma.sync.aligned.m16n8k16.row.col.f32.f16.f16.f32 "
        "{%0,%1,%2,%3}, {%4,%5,%6,%7}, {%8,%9}, {%0,%1,%2,%3};"
        : "+f"(d[0]), "+f"(d[1]), "+f"(d[2]), "+f"(d[3])
        : "r"(a[0]), "r"(a[1]), "r"(a[2]), "r"(a[3]), "r"(b0), "r"(b1));
}

// -------- fused prepass: blocks [0, DEQ) dequant W; [DEQ, DEQ+CVT) convert x --------
__global__ __launch_bounds__(256)
void prepass_kernel(const float* __restrict__ x,
                    const int* __restrict__ packed,
                    const float* __restrict__ scales,
                    const int* __restrict__ zeros)
{
    if (blockIdx.x < DEQ_BLOCKS) {
        size_t idx = (size_t)blockIdx.x * 256 + threadIdx.x;   // over N*K/8
        int n  = (int)(idx >> 9);
        int j4 = (int)(idx & 511);                             // 4 int32 -> 8 k
        int4 p = *reinterpret_cast<const int4*>(
            &packed[(size_t)n * (K_DIM / 2) + j4 * 4]);
        int g  = j4 >> 3;
        float s  = scales[(size_t)n * (K_DIM / GRP) + g];
        float zs = -(float)zeros[(size_t)n * (K_DIM / GRP) + g] * s;
        int pv[4] = {p.x, p.y, p.z, p.w};
        __half2 h[4];
        #pragma unroll
        for (int c = 0; c < 4; c++)
            h[c] = __floats2half2_rn((float)( pv[c]       & 15) * s + zs,
                                     (float)((pv[c] >> 4) & 15) * s + zs);
        *reinterpret_cast<uint4*>(&g_wh[(size_t)n * K_DIM + j4 * 8]) =
            *reinterpret_cast<uint4*>(h);
    } else {
        size_t idx = (size_t)(blockIdx.x - DEQ_BLOCKS) * 256 + threadIdx.x;
        const float4 v0 = *reinterpret_cast<const float4*>(x + idx * 8);
        const float4 v1 = *reinterpret_cast<const float4*>(x + idx * 8 + 4);
        __half2 h[4];
        h[0] = __floats2half2_rn(v0.x, v0.y);
        h[1] = __floats2half2_rn(v0.z, v0.w);
        h[2] = __floats2half2_rn(v1.x, v1.y);
        h[3] = __floats2half2_rn(v1.z, v1.w);
        *reinterpret_cast<uint4*>(&g_xh[idx * 8]) = *reinterpret_cast<uint4*>(h);
    }
}

// -------- GEMM: 128 threads, 64x64 warp tiles, cross-iter frag pipeline --------
__global__ __launch_bounds__(128, 2)
void gemm_fp16_kernel(const float* __restrict__ bias,
                      float* __restrict__ out)
{
    extern __shared__ __align__(16) __half smem[];
    __half* As = smem;                       // [NSTAGE][128][SROWH]
    __half* Bs = smem + NSTAGE * TILEH;

    const int tid    = threadIdx.x;
    const int lane   = tid & 31;
    const int wid    = tid >> 5;
    const int warp_m = wid & 1;              // 2 warps in m -> 64 rows each
    const int warp_n = wid >> 1;             // 2 warps in n -> 64 cols each
    const int m0 = blockIdx.x * BM;
    const int n0 = blockIdx.y * BN;

    const uint32_t as_u = smem_u32(As);
    const uint32_t bs_u = smem_u32(Bs);

    // cp.async: each tile = 512 16B chunks; 128 threads -> 4 chunks/thread/tile
    const int ld_row = tid >> 2;             // 0..31, +32 per i
    const int ld_c16 = tid & 3;              // 16B col within 64B row
    const __half* a_src = g_xh + (size_t)(m0 + ld_row) * K_DIM + ld_c16 * 8;
    const __half* b_src = g_wh + (size_t)(n0 + ld_row) * K_DIM + ld_c16 * 8;
    const uint32_t a_dst0 = as_u + (uint32_t)(ld_row * SROWH) * 2 + ld_c16 * 16;
    const uint32_t b_dst0 = bs_u + (uint32_t)(ld_row * SROWH) * 2 + ld_c16 * 16;

    float acc[4][8][4];
    #pragma unroll
    for (int i = 0; i < 4; i++)
        #pragma unroll
        for (int j = 0; j < 8; j++)
            #pragma unroll
            for (int r = 0; r < 4; r++) acc[i][j][r] = 0.0f;

    // prologue: stages 0..NSTAGE-2
    #pragma unroll
    for (int s = 0; s < NSTAGE - 1; s++) {
        const int k0 = s * BK;
        #pragma unroll
        for (int i = 0; i < 4; i++) {
            CP_ASYNC16(a_dst0 + (uint32_t)(s * TILEH + i * 32 * SROWH) * 2,
                       a_src + (size_t)i * 32 * K_DIM + k0);
            CP_ASYNC16(b_dst0 + (uint32_t)(s * TILEH + i * 32 * SROWH) * 2,
                       b_src + (size_t)i * 32 * K_DIM + k0);
        }
        CP_COMMIT();
    }

    // ldmatrix bases
    const uint32_t a_frag0 = as_u +
        (uint32_t)((warp_m * 64 + (lane & 15)) * SROWH + (lane >> 4) * 8) * 2;
    const uint32_t b_frag0 = bs_u +
        (uint32_t)((warp_n * 64 + ((lane >> 4) * 8) + (lane & 7)) * SROWH +
                   (((lane >> 3) & 1) * 8)) * 2;

    // preload iter-0 ks=0 fragments (stage 0 guaranteed by wait_group 1:
    // 3 groups committed, <=1 pending -> stages 0,1 landed)
    uint32_t a0[4][4], b0[4][4], a1[4][4], b1[4][4];
    asm volatile("cp.async.wait_group 1;" ::: "memory");
    __syncthreads();
    #pragma unroll
    for (int i = 0; i < 4; i++)
        ldsm_x4(a0[i], a_frag0 + (uint32_t)(i * 16 * SROWH) * 2);
    #pragma unroll
    for (int j2 = 0; j2 < 4; j2++)
        ldsm_x4(b0[j2], b_frag0 + (uint32_t)(j2 * 16 * SROWH) * 2);

    for (int it = 0; it < NITER; ++it) {
        // guarantee stage it+1 resident (3+it groups committed, <=1 pending)
        asm volatile("cp.async.wait_group 1;" ::: "memory");
        __syncthreads();   // all warps done reading buffer (it-1)&3 (iter it-1)

        // prefetch stage it+3 into buffer (it-1)&3
        const int pf = it + NSTAGE - 1;
        if (pf < NITER) {
            const int k0 = pf * BK;
            const uint32_t poff = (uint32_t)((pf & (NSTAGE - 1)) * TILEH) * 2;
            #pragma unroll
            for (int i = 0; i < 4; i++) {
                CP_ASYNC16(a_dst0 + poff + (uint32_t)(i * 32 * SROWH) * 2,
                           a_src + (size_t)i * 32 * K_DIM + k0);
                CP_ASYNC16(b_dst0 + poff + (uint32_t)(i * 32 * SROWH) * 2,
                           b_src + (size_t)i * 32 * K_DIM + k0);
            }
        }
        CP_COMMIT();   // one group per iter keeps counts aligned

        const uint32_t soff  = (uint32_t)((it & (NSTAGE - 1)) * TILEH) * 2;
        const uint32_t soffn = (uint32_t)(((it + 1) & (NSTAGE - 1)) * TILEH) * 2;

        // ks=1 fragments (stage it) — issue before ks=0 MMAs to hide latency
        #pragma unroll
        for (int i = 0; i < 4; i++)
            ldsm_x4(a1[i], a_frag0 + soff + (uint32_t)(i * 16 * SROWH + 16) * 2);
        #pragma unroll
        for (int j2 = 0; j2 < 4; j2++)
            ldsm_x4(b1[j2], b_frag0 + soff + (uint32_t)(j2 * 16 * SROWH + 16) * 2);

        // ks=0 MMAs (fragments were loaded at tail of previous iteration)
        #pragma unroll
        for (int i = 0; i < 4; i++)
            #pragma unroll
            for (int j = 0; j < 8; j++)
                mma_fp16(acc[i][j], a0[i], b0[j >> 1][(j & 1) * 2],
                         b0[j >> 1][(j & 1) * 2 + 1]);

        // tail-load next iteration's ks=0 fragments (stage it+1, resident),
        // reusing a0/b0 after the ks=0 MMAs consumed them (WAR, in-order asm)
        if (it + 1 < NITER) {
            #pragma unroll
            for (int i = 0; i < 4; i++)
                ldsm_x4(a0[i], a_frag0 + soffn + (uint32_t)(i * 16 * SROWH) * 2);
            #pragma unroll
            for (int j2 = 0; j2 < 4; j2++)
                ldsm_x4(b0[j2], b_frag0 + soffn + (uint32_t)(j2 * 16 * SROWH) * 2);
        }

        // ks=1 MMAs
        #pragma unroll
        for (int i = 0; i < 4; i++)
            #pragma unroll
            for (int j = 0; j < 8; j++)
                mma_fp16(acc[i][j], a1[i], b1[j >> 1][(j & 1) * 2],
                         b1[j >> 1][(j & 1) * 2 + 1]);
    }

    // -------- epilogue: bias + store --------
    #pragma unroll
    for (int i = 0; i < 4; i++) {
        const int mrow = m0 + warp_m * 64 + i * 16 + (lane >> 2);
        #pragma unroll
        for (int j = 0; j < 8; j++) {
            const int n = n0 + warp_n * 64 + j * 8 + 2 * (lane & 3);
            const float bb0 = bias[n], bb1 = bias[n + 1];
            float2 v0 = make_float2(acc[i][j][0] + bb0, acc[i][j][1] + bb1);
            float2 v1 = make_float2(acc[i][j][2] + bb0, acc[i][j][3] + bb1);
            *reinterpret_cast<float2*>(out + (size_t)mrow * N_DIM + n) = v0;
            *reinterpret_cast<float2*>(out + (size_t)(mrow + 8) * N_DIM + n) = v1;
        }
    }
}

// -------- launch --------
extern "C" void kernel_launch(void* const* d_in, const int* in_sizes, int n_in,
                              void* d_out, int out_size)
{
    const float* x      = (const float*)d_in[0];
    const int*   packed = (const int*)  d_in[1];
    const float* scales = (const float*)d_in[2];
    const int*   zeros  = (const int*)  d_in[3];
    const float* bias   = (const float*)d_in[4];
    float*       out    = (float*)d_out;

    static int smem_set = 0;
    if (!smem_set) {
        cudaFuncSetAttribute(gemm_fp16_kernel,
                             cudaFuncAttributeMaxDynamicSharedMemorySize, SMEM_SZ);
        smem_set = 1;
    }

    prepass_kernel<<<DEQ_BLOCKS + CVT_BLOCKS, 256>>>(x, packed, scales, zeros);

    dim3 grid(M_DIM / BM, N_DIM / BN);   // 32 x 86; m fastest -> A stays L2-resident
    gemm_fp16_kernel<<<grid, 128, SMEM_SZ>>>(bias, out);
}